// round 12
// baseline (speedup 1.0000x reference)
#include <cuda_runtime.h>
#include <math.h>

#define PAD 68
#define ARR (64 * PAD)
#define SMEM_FLOATS (3 * ARR + 32)
#define SMEM_BYTES (SMEM_FLOATS * 4)

typedef unsigned long long u64;

// column-softmaxed weights, o-major: g_wT[o*64 + i] = w[i][o]
__device__ float g_wT[64 * 64];

static __device__ __forceinline__ u64 ffma2(u64 a, u64 b, u64 c) {
    u64 d; asm("fma.rn.f32x2 %0,%1,%2,%3;" : "=l"(d) : "l"(a), "l"(b), "l"(c)); return d;
}
static __device__ __forceinline__ u64 fmul2(u64 a, u64 b) {
    u64 d; asm("mul.rn.f32x2 %0,%1,%2;" : "=l"(d) : "l"(a), "l"(b)); return d;
}
static __device__ __forceinline__ float hadd2(u64 v) {
    float lo, hi; asm("mov.b64 {%0,%1},%2;" : "=f"(lo), "=f"(hi) : "l"(v));
    return lo + hi;
}
static __device__ __forceinline__ void unpack2(u64 v, float& lo, float& hi) {
    asm("mov.b64 {%0,%1},%2;" : "=f"(lo), "=f"(hi) : "l"(v));
}
static __device__ __forceinline__ u64 bcast2(float f) {
    u64 d; asm("mov.b64 %0,{%1,%1};" : "=l"(d) : "f"(f)); return d;
}

// acos via A&S 4.4.45 7-term poly, Estrin form: abs err ~2e-8 on [-1,1]
// Input always pre-clamped to |x| <= 1-1e-7, so om >= 1e-7 (rsqrt safe).
static __device__ __forceinline__ float acos_fast(float x) {
    float ax = fabsf(x);
    float om = 1.0f - ax;
    float s = om * rsqrtf(om);   // sqrt(1-ax), MUFU issued early
    float x2 = ax * ax;
    float x4 = x2 * x2;
    float p01 = fmaf(ax, -0.2145988016f, 1.5707963050f);
    float p23 = fmaf(ax, -0.0501743046f, 0.0889789874f);
    float p45 = fmaf(ax, -0.0170881256f, 0.0308918810f);
    float p67 = fmaf(ax, -0.0012624911f, 0.0066700901f);
    float q0 = fmaf(p23, x2, p01);
    float q1 = fmaf(p67, x2, p45);
    float p = fmaf(q1, x4, q0);
    float r = p * s;
    return (x < 0.0f) ? 3.14159265358979f - r : r;
}

__global__ void wprep_kernel(const float* __restrict__ wraw) {
    int o = threadIdx.x;  // 64 threads, one output column each
    float s = 0.f;
    #pragma unroll 8
    for (int i = 0; i < 64; ++i) s += expf(wraw[i * 64 + o]);
    float inv = 1.0f / s;
    #pragma unroll 8
    for (int i = 0; i < 64; ++i) g_wT[o * 64 + i] = expf(wraw[i * 64 + o]) * inv;
}

__global__ __launch_bounds__(128, 4) void mfd_kernel(const float* __restrict__ xg,
                                                     float* __restrict__ out) {
    extern __shared__ float sm[];
    float* Xs  = sm;              // [64][PAD]  x rows (dd-contiguous)
    float* As  = Xs + ARR;        // [64][PAD]  current iterate a
    float* Fs  = As + ARR;        // [64][PAD]  F matrix (i-contiguous per o-row)

    const int n   = blockIdx.x;
    const int tid = threadIdx.x;
    const int oc  = tid >> 4;     // 0..7  (warp = {2w, 2w+1} oc values)
    const int ic  = tid & 15;     // 0..15

    // ---- load x tile (coalesced float4) ----
    const float* xn = xg + (size_t)n * 4096;
    for (int t = tid; t < 1024; t += 128) {
        float4 v = ((const float4*)xn)[t];
        int r = t >> 4, c = (t & 15) << 2;
        *(float4*)&Xs[r * PAD + c] = v;
    }
    __syncthreads();

    // ---- init a_o = x_0 for all o ----
    for (int t = tid; t < 1024; t += 128) {
        int r = t >> 4, c = (t & 15) << 2;
        *(float4*)&As[r * PAD + c] = *(float4*)&Xs[c];
    }
    __syncthreads();
    // Unit-norm inputs; exp-map preserves unit norm to rounding:
    // ||v||^2 = 1 - dc^2 and ||grad||^2 = P - 2*corr*Q + corr^2.
    // Warps own their As/Fs rows (o = oc + 8k) -> warp-local sync inside loop.

    const float HI = 1.0f - 1e-7f;

    #pragma unroll 1
    for (int it = 0; it < 3; ++it) {
        float corr[8];

        if (it == 0) {
            // ===== iter-0: D[o][i] = x0 . x_i for ALL o -> 4 direct dots =====
            u64 dp2[4];
            #pragma unroll
            for (int j = 0; j < 4; ++j) dp2[j] = 0ull;
            #pragma unroll 4
            for (int dd = 0; dd < 64; dd += 4) {
                ulonglong2 x0p = *(const ulonglong2*)&Xs[dd];  // row 0, broadcast
                #pragma unroll
                for (int j = 0; j < 4; ++j) {
                    ulonglong2 xp = *(const ulonglong2*)&Xs[(ic + 16 * j) * PAD + dd];
                    dp2[j] = ffma2(x0p.x, xp.x, dp2[j]);
                    dp2[j] = ffma2(x0p.y, xp.y, dp2[j]);
                }
            }
            float dcv[4], ffv[4];
            #pragma unroll
            for (int j = 0; j < 4; ++j) {
                float draw = hadd2(dp2[j]);
                float dc   = fminf(fmaxf(draw, -HI), HI);
                dcv[j] = dc;
                ffv[j] = acos_fast(dc) * rsqrtf(fmaf(-dc, dc, 1.0f));
            }
            #pragma unroll
            for (int k = 0; k < 8; ++k) {
                int o = oc + 8 * k;
                float cr = 0.f;
                #pragma unroll
                for (int j = 0; j < 4; ++j) {
                    int i = ic + 16 * j;
                    float F = g_wT[o * 64 + i] * ffv[j];
                    Fs[o * PAD + i] = F;
                    cr = fmaf(F, dcv[j], cr);
                }
                corr[k] = cr;
            }
        } else {
            // ===== GEMM1 (f32x2 along dd): D[o][i] = sum_dd A[o][dd]*X[i][dd]
            u64 acc2[8][4];
            #pragma unroll
            for (int k = 0; k < 8; ++k)
                #pragma unroll
                for (int j = 0; j < 4; ++j) acc2[k][j] = 0ull;

            #pragma unroll 4
            for (int dd = 0; dd < 64; dd += 4) {
                ulonglong2 xp[4];
                #pragma unroll
                for (int j = 0; j < 4; ++j)
                    xp[j] = *(const ulonglong2*)&Xs[(ic + 16 * j) * PAD + dd];
                #pragma unroll
                for (int k = 0; k < 8; ++k) {
                    ulonglong2 ap = *(const ulonglong2*)&As[(oc + 8 * k) * PAD + dd];
                    #pragma unroll
                    for (int j = 0; j < 4; ++j) {
                        acc2[k][j] = ffma2(ap.x, xp[j].x, acc2[k][j]);
                        acc2[k][j] = ffma2(ap.y, xp[j].y, acc2[k][j]);
                    }
                }
            }

            // ===== F[o][i] = w[i][o]*theta/||v||, partial corr = sum_i F*dc
            #pragma unroll
            for (int k = 0; k < 8; ++k) {
                int o = oc + 8 * k;
                float cr = 0.f;
                #pragma unroll
                for (int j = 0; j < 4; ++j) {
                    int i = ic + 16 * j;
                    float draw  = hadd2(acc2[k][j]);
                    float dc    = fminf(fmaxf(draw, -HI), HI);
                    float theta = acos_fast(dc);
                    float nv2   = fmaf(-dc, dc, 1.0f);
                    float f     = theta * rsqrtf(nv2);
                    float F     = g_wT[o * 64 + i] * f;
                    Fs[o * PAD + i] = F;
                    cr = fmaf(F, dc, cr);
                }
                corr[k] = cr;
            }
        }
        __syncwarp();  // warp's Fs rows complete

        // ===== GEMM2 (f32x2 along dd-pairs, F broadcast):
        //       G[o][dd] = sum_i F[o][i] * X[i][dd]
        //       thread owns dd in {2ic, 2ic+1} and {2ic+32, 2ic+33}
        u64 g2[8][2];
        #pragma unroll
        for (int k = 0; k < 8; ++k) { g2[k][0] = 0ull; g2[k][1] = 0ull; }

        const int dlo = 2 * ic, dhi = 2 * ic + 32;
        #pragma unroll 4
        for (int i4 = 0; i4 < 64; i4 += 4) {
            u64 xl[4], xh[4];
            #pragma unroll
            for (int r = 0; r < 4; ++r) {
                xl[r] = *(const u64*)&Xs[(i4 + r) * PAD + dlo];
                xh[r] = *(const u64*)&Xs[(i4 + r) * PAD + dhi];
            }
            #pragma unroll
            for (int k = 0; k < 8; ++k) {
                ulonglong2 fp = *(const ulonglong2*)&Fs[(oc + 8 * k) * PAD + i4];
                float f0, f1, f2, f3;
                unpack2(fp.x, f0, f1);
                unpack2(fp.y, f2, f3);
                u64 b0 = bcast2(f0), b1 = bcast2(f1), b2 = bcast2(f2), b3 = bcast2(f3);
                g2[k][0] = ffma2(b0, xl[0], g2[k][0]);
                g2[k][0] = ffma2(b1, xl[1], g2[k][0]);
                g2[k][0] = ffma2(b2, xl[2], g2[k][0]);
                g2[k][0] = ffma2(b3, xl[3], g2[k][0]);
                g2[k][1] = ffma2(b0, xh[0], g2[k][1]);
                g2[k][1] = ffma2(b1, xh[1], g2[k][1]);
                g2[k][1] = ffma2(b2, xh[2], g2[k][1]);
                g2[k][1] = ffma2(b3, xh[3], g2[k][1]);
            }
        }

        // ===== epilogue, fissioned =====
        // load a rows (independent of reductions)
        u64 a0v[8], a1v[8];
        #pragma unroll
        for (int k = 0; k < 8; ++k) {
            int o = oc + 8 * k;
            a0v[k] = *(const u64*)&As[o * PAD + dlo];
            a1v[k] = *(const u64*)&As[o * PAD + dhi];
        }
        // per-k partials: P = sum G^2, Q = sum G.a
        float Pv[8], Qv[8];
        #pragma unroll
        for (int k = 0; k < 8; ++k) {
            u64 pp = ffma2(g2[k][0], g2[k][0], fmul2(g2[k][1], g2[k][1]));
            u64 qq = ffma2(g2[k][0], a0v[k],  fmul2(g2[k][1], a1v[k]));
            Pv[k] = hadd2(pp);
            Qv[k] = hadd2(qq);
        }
        // one batch of 24 interleaved butterfly trees (corr, P, Q)
        #pragma unroll
        for (int s = 1; s < 16; s <<= 1) {
            #pragma unroll
            for (int k = 0; k < 8; ++k) {
                corr[k] += __shfl_xor_sync(0xffffffffu, corr[k], s);
                Pv[k]   += __shfl_xor_sync(0xffffffffu, Pv[k],   s);
                Qv[k]   += __shfl_xor_sync(0xffffffffu, Qv[k],   s);
            }
        }
        // scalar tail: gn2 = P - 2*corr*Q + corr^2 ; sincos; u = cg - sc*corr
        float scv[8], uv[8];
        #pragma unroll
        for (int k = 0; k < 8; ++k) {
            float cr = corr[k];
            float gn2 = fmaf(cr, cr, fmaf(-2.0f * cr, Qv[k], Pv[k]));
            gn2 = fmaxf(gn2, 0.0f);                 // guard cancellation
            float inv = rsqrtf(fmaxf(gn2, 1e-30f));
            float gn = gn2 * inv;                   // sqrt(gn2)
            float sg, cg;
            __sincosf(gn, &sg, &cg);
            float sc = (gn2 < 1e-14f) ? 1.0f : sg * inv;
            if (gn2 < 1e-14f) cg = 1.0f;
            scv[k] = sc;
            uv[k]  = fmaf(-sc, cr, cg);             // cg - sc*corr
        }
        // a_new = u*a + sc*G
        #pragma unroll
        for (int k = 0; k < 8; ++k) {
            int o = oc + 8 * k;
            u64 ub = bcast2(uv[k]), scb = bcast2(scv[k]);
            u64 an0 = ffma2(ub, a0v[k], fmul2(scb, g2[k][0]));
            u64 an1 = ffma2(ub, a1v[k], fmul2(scb, g2[k][1]));
            if (it == 2) {
                *(u64*)&out[(size_t)n * 4096 + o * 64 + dlo] = an0;
                *(u64*)&out[(size_t)n * 4096 + o * 64 + dhi] = an1;
            } else {
                *(u64*)&As[o * PAD + dlo] = an0;
                *(u64*)&As[o * PAD + dhi] = an1;
            }
        }
        __syncwarp();  // warp's As rows ready for its next iteration
    }
}

extern "C" void kernel_launch(void* const* d_in, const int* in_sizes, int n_in,
                              void* d_out, int out_size) {
    const float* x    = (const float*)d_in[0];   // (4,256,64,64)
    const float* wraw = (const float*)d_in[1];   // (64,64)
    float* out = (float*)d_out;                  // (4,256,64,64)

    cudaFuncSetAttribute(mfd_kernel, cudaFuncAttributeMaxDynamicSharedMemorySize, SMEM_BYTES);

    wprep_kernel<<<1, 64>>>(wraw);
    mfd_kernel<<<1024, 128, SMEM_BYTES>>>(x, out);
}